// round 4
// baseline (speedup 1.0000x reference)
#include <cuda_runtime.h>
#include <math.h>

#define NB 64
#define NC 2048
#define ND 256
#define NM 196
#define NITER 18
#define MATN 65536
#define NBM (NB*MATN)
#define RIDGE 1e-5f
#define TRI 32896

// ---------------- static device scratch (no allocations) ----------------
__device__ float g_y[NB*ND*NM];     // conv output [b][o][m]
__device__ float g_zc[NBM];         // centered padded [b][o][0..255]
__device__ float g_G[NBM];          // Gram, later W
__device__ float g_Ybuf[2*NBM];     // NS Y ping-pong
__device__ float g_Zbuf[2*NBM];     // NS Z ping-pong
__device__ float g_T[NBM];
__device__ float g_scale[ND];
__device__ float g_shift[ND];
__device__ float g_innrm[NB];
__device__ float g_qscale[NB];

// =====================================================================
// conv: y[b,o,m] = sum_c w[o,c]*x[b,c,m].  64x64x16 tile GEMM.
// grid (196, 4), 256 threads
// =====================================================================
__global__ __launch_bounds__(256) void conv_kernel(const float* __restrict__ w,
                                                   const float* __restrict__ x) {
    __shared__ float As[16][68];
    __shared__ float Bs[16][68];
    const int bn = blockIdx.x * 64;           // n = b*196+m
    const int bm = blockIdx.y * 64;           // o
    const int tid = threadIdx.x;
    const int ty = tid >> 4, tx = tid & 15;

    const int cB = tid & 63;
    const int krB = tid >> 6;                 // 0..3
    const int n0 = bn + cB;
    const int b0 = n0 / NM;
    const int m0 = n0 - b0 * NM;
    const float* xb = x + (size_t)b0 * NC * NM + m0;

    const int rA = tid >> 4;                  // 0..15
    const int cA = tid & 15;                  // 0..15
    const float* wrow = w + (size_t)(bm + rA) * NC + cA;

    float acc[4][4];
#pragma unroll
    for (int i = 0; i < 4; i++)
#pragma unroll
        for (int j = 0; j < 4; j++) acc[i][j] = 0.f;

    for (int k0 = 0; k0 < NC; k0 += 16) {
#pragma unroll
        for (int u = 0; u < 4; u++)
            As[cA][rA + u*16] = wrow[(size_t)(u*16) * NC + k0];
#pragma unroll
        for (int u = 0; u < 4; u++)
            Bs[krB + u*4][cB] = xb[(size_t)(k0 + krB + u*4) * NM];
        __syncthreads();
#pragma unroll
        for (int k = 0; k < 16; k++) {
            float a4[4], b4[4];
            *(float4*)a4 = *(const float4*)&As[k][ty*4];
            *(float4*)b4 = *(const float4*)&Bs[k][tx*4];
#pragma unroll
            for (int i = 0; i < 4; i++)
#pragma unroll
                for (int j = 0; j < 4; j++)
                    acc[i][j] = fmaf(a4[i], b4[j], acc[i][j]);
        }
        __syncthreads();
    }
#pragma unroll
    for (int j = 0; j < 4; j++) {
        int nn = bn + tx*4 + j;
        int bb = nn / NM;
        int mm = nn - bb*NM;
#pragma unroll
        for (int i = 0; i < 4; i++) {
            int o = bm + ty*4 + i;
            g_y[(size_t)bb*(ND*NM) + o*NM + mm] = acc[i][j];
        }
    }
}

// =====================================================================
// BN stats per channel o over (b,m): scale/shift
// =====================================================================
__global__ __launch_bounds__(256) void bn_stats_kernel(const float* __restrict__ gamma,
                                                       const float* __restrict__ beta) {
    int o = blockIdx.x, t = threadIdx.x;
    float s = 0.f, ss = 0.f;
    for (int i = t; i < NB*NM; i += 256) {
        int b = i / NM;
        int m = i - b*NM;
        float v = g_y[(size_t)b*(ND*NM) + o*NM + m];
        s += v; ss = fmaf(v, v, ss);
    }
    __shared__ float r1[256], r2[256];
    r1[t] = s; r2[t] = ss; __syncthreads();
    for (int st = 128; st > 0; st >>= 1) {
        if (t < st) { r1[t] += r1[t+st]; r2[t] += r2[t+st]; }
        __syncthreads();
    }
    if (t == 0) {
        const float inv_n = 1.f / (float)(NB*NM);
        float mean = r1[0] * inv_n;
        float var  = fmaf(-mean, mean, r2[0] * inv_n);
        float isd  = rsqrtf(var + 1e-5f);
        float sc = gamma[o] * isd;
        g_scale[o] = sc;
        g_shift[o] = fmaf(-mean, sc, beta[o]);
    }
}

// =====================================================================
// BN apply + ReLU + per-(b,o) centering over m; write padded zc
// grid 64*256 blocks, 256 threads
// =====================================================================
__global__ __launch_bounds__(256) void center_kernel() {
    int bid = blockIdx.x;
    int b = bid >> 8, o = bid & 255;
    int t = threadIdx.x;
    float v = 0.f;
    if (t < NM) {
        float raw = g_y[(size_t)b*(ND*NM) + o*NM + t];
        v = fmaxf(fmaf(raw, g_scale[o], g_shift[o]), 0.f);
    }
    __shared__ float red[256];
    red[t] = v; __syncthreads();
    for (int s = 128; s > 0; s >>= 1) {
        if (t < s) red[t] += red[t+s];
        __syncthreads();
    }
    float mean = red[0] * (1.f / (float)NM);
    g_zc[(size_t)b*MATN + o*256 + t] = (t < NM) ? (v - mean) : 0.f;
}

// =====================================================================
// Generic batched 256x256x256 SGEMM, 128x128x16 tile, 8x8 microtile.
// TA: op(A)=A^T, TB: op(B)=B^T. EPI: 0 plain, 1 T=(3I-P)/2, 2 packed-triu out.
// grid (2,2,64), 256 threads
// =====================================================================
template<bool TA, bool TB, int EPI>
__global__ __launch_bounds__(256) void gemm256(const float* __restrict__ Abase,
                                               const float* __restrict__ Bbase,
                                               float* __restrict__ Cbase) {
    if (EPI == 2 && blockIdx.y > blockIdx.x) return;  // strictly below diagonal
    __shared__ float As[16][132];
    __shared__ float Bs[16][132];
    const int b  = blockIdx.z;
    const int i0 = blockIdx.y * 128;
    const int j0 = blockIdx.x * 128;
    const float* A = Abase + (size_t)b * MATN;
    const float* B = Bbase + (size_t)b * MATN;
    const int tid = threadIdx.x;
    const int ty = tid >> 4, tx = tid & 15;

    float acc[8][8];
#pragma unroll
    for (int i = 0; i < 8; i++)
#pragma unroll
        for (int j = 0; j < 8; j++) acc[i][j] = 0.f;

    for (int k0 = 0; k0 < 256; k0 += 16) {
        if (TA) {  // As[k][i] = A[(k0+k)*256 + i0+i]
            int i4 = (tid & 31) * 4;
            int kb = tid >> 5;
#pragma unroll
            for (int u = 0; u < 2; u++) {
                int k = kb + u*8;
                float4 v = *(const float4*)&A[(size_t)(k0+k)*256 + i0 + i4];
                As[k][i4+0]=v.x; As[k][i4+1]=v.y; As[k][i4+2]=v.z; As[k][i4+3]=v.w;
            }
        } else {   // As[k][i] = A[(i0+i)*256 + k0+k]
            int k4 = (tid & 3) * 4;
            int ib = tid >> 2;
#pragma unroll
            for (int u = 0; u < 2; u++) {
                int i = ib + u*64;
                float4 v = *(const float4*)&A[(size_t)(i0+i)*256 + k0 + k4];
                As[k4+0][i]=v.x; As[k4+1][i]=v.y; As[k4+2][i]=v.z; As[k4+3][i]=v.w;
            }
        }
        if (TB) {  // Bs[k][j] = B[(j0+j)*256 + k0+k]
            int k4 = (tid & 3) * 4;
            int jb = tid >> 2;
#pragma unroll
            for (int u = 0; u < 2; u++) {
                int j = jb + u*64;
                float4 v = *(const float4*)&B[(size_t)(j0+j)*256 + k0 + k4];
                Bs[k4+0][j]=v.x; Bs[k4+1][j]=v.y; Bs[k4+2][j]=v.z; Bs[k4+3][j]=v.w;
            }
        } else {   // Bs[k][j] = B[(k0+k)*256 + j0+j]
            int j4 = (tid & 31) * 4;
            int kb = tid >> 5;
#pragma unroll
            for (int u = 0; u < 2; u++) {
                int k = kb + u*8;
                float4 v = *(const float4*)&B[(size_t)(k0+k)*256 + j0 + j4];
                Bs[k][j4+0]=v.x; Bs[k][j4+1]=v.y; Bs[k][j4+2]=v.z; Bs[k][j4+3]=v.w;
            }
        }
        __syncthreads();
#pragma unroll
        for (int k = 0; k < 16; k++) {
            float av[8], bv[8];
            *(float4*)&av[0] = *(const float4*)&As[k][ty*8];
            *(float4*)&av[4] = *(const float4*)&As[k][ty*8+4];
            *(float4*)&bv[0] = *(const float4*)&Bs[k][tx*8];
            *(float4*)&bv[4] = *(const float4*)&Bs[k][tx*8+4];
#pragma unroll
            for (int i = 0; i < 8; i++)
#pragma unroll
                for (int j = 0; j < 8; j++)
                    acc[i][j] = fmaf(av[i], bv[j], acc[i][j]);
        }
        __syncthreads();
    }

    const int r0 = i0 + ty*8, c0 = j0 + tx*8;
    if (EPI == 0) {
        float* C = Cbase + (size_t)b * MATN;
#pragma unroll
        for (int i = 0; i < 8; i++) {
            *(float4*)&C[(size_t)(r0+i)*256 + c0]     = *(float4*)&acc[i][0];
            *(float4*)&C[(size_t)(r0+i)*256 + c0 + 4] = *(float4*)&acc[i][4];
        }
    } else if (EPI == 1) {
        float* C = Cbase + (size_t)b * MATN;
#pragma unroll
        for (int i = 0; i < 8; i++) {
            int r = r0 + i;
#pragma unroll
            for (int j = 0; j < 8; j++)
                acc[i][j] = fmaf(-0.5f, acc[i][j], (r == c0+j) ? 1.5f : 0.f);
            *(float4*)&C[(size_t)r*256 + c0]     = *(float4*)&acc[i][0];
            *(float4*)&C[(size_t)r*256 + c0 + 4] = *(float4*)&acc[i][4];
        }
    } else {
        float s = g_qscale[b];
        float* O = Cbase + (size_t)b * TRI;
#pragma unroll
        for (int i = 0; i < 8; i++) {
            int r = r0 + i;
            int rowbase = r*256 - (r*(r-1))/2 - r;
#pragma unroll
            for (int j = 0; j < 8; j++) {
                int c = c0 + j;
                if (r <= c) O[rowbase + c] = acc[i][j] * s;
            }
        }
    }
}

// =====================================================================
// Frobenius norm of G per batch -> 1/nrm and Q output scale
// =====================================================================
__global__ __launch_bounds__(256) void frob_kernel() {
    int b = blockIdx.x, t = threadIdx.x;
    const float* G = g_G + (size_t)b * MATN;
    float s = 0.f;
    for (int i = t; i < MATN; i += 256) { float v = G[i]; s = fmaf(v, v, s); }
    __shared__ float red[256];
    red[t] = s; __syncthreads();
    for (int st = 128; st > 0; st >>= 1) {
        if (t < st) red[t] += red[t+st];
        __syncthreads();
    }
    if (t == 0) {
        float nrm = sqrtf(red[0]);
        g_innrm[b]  = 1.f / nrm;
        g_qscale[b] = rsqrtf(nrm * (float)NM);
    }
}

// Y0 = G/nrm + RIDGE*I ; Z0 = I.   grid (256, 64), 256 threads
__global__ __launch_bounds__(256) void init_kernel() {
    int b = blockIdx.y, r = blockIdx.x, c = threadIdx.x;
    size_t idx = (size_t)b*MATN + r*256 + c;
    float diag = (r == c) ? 1.f : 0.f;
    g_Ybuf[idx] = fmaf(g_G[idx], g_innrm[b], diag * RIDGE);
    g_Zbuf[idx] = diag;
}

// =====================================================================
static float* symaddr(const void* sym) {
    void* p = nullptr;
    cudaGetSymbolAddress(&p, sym);
    return (float*)p;
}

extern "C" void kernel_launch(void* const* d_in, const int* in_sizes, int n_in,
                              void* d_out, int out_size) {
    const float* x     = (const float*)d_in[0];
    const float* w     = (const float*)d_in[1];
    const float* gamma = (const float*)d_in[2];
    const float* beta  = (const float*)d_in[3];
    float* out = (float*)d_out;

    float* pZc = symaddr(g_zc);
    float* pG  = symaddr(g_G);
    float* pY  = symaddr(g_Ybuf);
    float* pZ  = symaddr(g_Zbuf);
    float* pT  = symaddr(g_T);

    conv_kernel<<<dim3(196, 4), 256>>>(w, x);
    bn_stats_kernel<<<256, 256>>>(gamma, beta);
    center_kernel<<<NB*ND, 256>>>();

    dim3 g(2, 2, NB);
    // G = Zc^T Zc
    gemm256<true, false, 0><<<g, 256>>>(pZc, pZc, pG);
    frob_kernel<<<NB, 256>>>();
    init_kernel<<<dim3(256, NB), 256>>>();

    int cur = 0;
    for (int it = 0; it < NITER; it++) {
        float* Yc = pY + (size_t)cur * NBM;
        float* Zc = pZ + (size_t)cur * NBM;
        float* Yn = pY + (size_t)(1-cur) * NBM;
        float* Zn = pZ + (size_t)(1-cur) * NBM;
        gemm256<false, false, 1><<<g, 256>>>(Zc, Yc, pT);   // T = 1.5I - 0.5 Z*Y
        if (it != NITER-1)
            gemm256<false, false, 0><<<g, 256>>>(Yc, pT, Yn);  // Y' = Y*T
        gemm256<false, false, 0><<<g, 256>>>(pT, Zc, Zn);      // Z' = T*Z
        cur ^= 1;
    }
    // W = Zc * Z_final  (reuse g_G)
    gemm256<false, false, 0><<<g, 256>>>(pZc, pZ + (size_t)cur * NBM, pG);
    // Q = W * Zc^T * qscale -> packed upper triangle
    gemm256<false, true, 2><<<g, 256>>>(pG, pZc, out);
}